// round 2
// baseline (speedup 1.0000x reference)
#include <cuda_runtime.h>
#include <cstdint>

#define NA 50000
#define NE 500000
#define H  128
#define R  20
#define H3 (3*H)

static constexpr float PI_F = 3.14159265358979323846f;
static constexpr float PI_OVER_CUT = PI_F / 6.0f;   // pi / CUTOFF

// ---------------- scratch (static device globals; no allocations) ------------
__device__ float g_ns   [NA * H];        // node scalar
__device__ float g_nv   [NA * H3];       // node vector [N,3,H]
__device__ float g_dnv  [NA * H3];       // vector message accumulator (delta)
__device__ float g_s    [NA * H3];       // message MLP output s [N,3H]
__device__ float g_a    [NA * H3];       // update MLP output a [N,3H]
__device__ float g_hid  [NA * H];        // MLP hidden scratch
__device__ float g_mlpin[NA * 2 * H];    // concat(ns, Vnorm)
__device__ float g_Uv   [NA * H3];
__device__ float g_Vv   [NA * H3];
__device__ float g_rbf  [NE * R];        // rbf * fcut  (SORTED order)
__device__ float g_unit [NE * 3];        // (SORTED order)
__device__ float g_fcut [NE];            // (SORTED order)
__device__ float g_dist [NE];            // ORIGINAL edge order (output)

// edge sort-by-col structures
__device__ int g_cnt  [NA + 1];
__device__ int g_start[NA + 1];
__device__ int g_ofs  [NA];
__device__ int g_perm [NE];              // sorted slot -> original edge id
__device__ int g_srow [NE];              // row per sorted slot

__device__ __forceinline__ float silu_f(float x) { return x / (1.0f + __expf(-x)); }

// ---------------- init: ns = embed[z], nv = 0, dnv = 0, cnt = 0 --------------
__global__ void init_kernel(const int* __restrict__ z, const float* __restrict__ embed)
{
    int idx = blockIdx.x * blockDim.x + threadIdx.x;
    int total = NA * H3;
    for (int i = idx; i < total; i += gridDim.x * blockDim.x) {
        g_nv[i]  = 0.0f;
        g_dnv[i] = 0.0f;
        if (i < NA * H) {
            int n = i / H, h = i - n * H;
            g_ns[i] = embed[z[n] * H + h];
        }
        if (i <= NA) g_cnt[i] = 0;
    }
}

// ---------------- histogram over col -----------------------------------------
__global__ void hist_kernel(const int* __restrict__ eidx)
{
    int e = blockIdx.x * blockDim.x + threadIdx.x;
    if (e >= NE) return;
    atomicAdd(&g_cnt[eidx[NE + e]], 1);
}

// ---------------- single-block exclusive scan over 50k counts ----------------
__global__ __launch_bounds__(1024) void scan_kernel()
{
    __shared__ int part[1024];
    const int CH = (NA + 1023) / 1024;   // 49
    int t = threadIdx.x;
    int base = t * CH;
    int sum = 0;
    for (int i = 0; i < CH; i++) {
        int idx = base + i;
        if (idx < NA) sum += g_cnt[idx];
    }
    part[t] = sum;
    __syncthreads();
    for (int off = 1; off < 1024; off <<= 1) {
        int v = 0;
        if (t >= off) v = part[t - off];
        __syncthreads();
        part[t] += v;
        __syncthreads();
    }
    int run = (t == 0) ? 0 : part[t - 1];
    for (int i = 0; i < CH; i++) {
        int idx = base + i;
        if (idx < NA) {
            int c = g_cnt[idx];
            g_start[idx] = run;
            g_ofs[idx]   = run;
            run += c;
        }
    }
    if (t == 1023) g_start[NA] = NE;
}

// ---------------- scatter into sorted order ----------------------------------
__global__ void scatter_kernel(const int* __restrict__ eidx)
{
    int e = blockIdx.x * blockDim.x + threadIdx.x;
    if (e >= NE) return;
    int c = eidx[NE + e];
    int p = atomicAdd(&g_ofs[c], 1);
    g_perm[p] = e;
    g_srow[p] = eidx[e];
}

// ---------------- edge geometry into SORTED slots ----------------------------
__global__ void edge_geom_kernel(const float* __restrict__ pos,
                                 const float* __restrict__ cell,
                                 const int*   __restrict__ eidx,
                                 const int*   __restrict__ coff)
{
    int i = blockIdx.x * blockDim.x + threadIdx.x;
    if (i >= NE) return;
    int e   = g_perm[i];
    int row = eidx[e];
    int col = eidx[NE + e];
    float ox = (float)coff[e * 3 + 0];
    float oy = (float)coff[e * 3 + 1];
    float oz = (float)coff[e * 3 + 2];
    float offx = ox * cell[0] + oy * cell[3] + oz * cell[6];
    float offy = ox * cell[1] + oy * cell[4] + oz * cell[7];
    float offz = ox * cell[2] + oy * cell[5] + oz * cell[8];
    float dx = pos[row * 3 + 0] - pos[col * 3 + 0] + offx;
    float dy = pos[row * 3 + 1] - pos[col * 3 + 1] + offy;
    float dz = pos[row * 3 + 2] - pos[col * 3 + 2] + offz;
    float d  = sqrtf(dx * dx + dy * dy + dz * dz);
    float inv = 1.0f / d;
    g_dist[e] = d;                        // original order for output
    g_unit[i * 3 + 0] = dx * inv;
    g_unit[i * 3 + 1] = dy * inv;
    g_unit[i * 3 + 2] = dz * inv;
    float fc = (d < 6.0f) ? 0.5f * (cosf(PI_F * d * (1.0f / 6.0f)) + 1.0f) : 0.0f;
    g_fcut[i] = fc;
#pragma unroll
    for (int r = 0; r < R; r++) {
        float arg = d * (float)(r + 1) * PI_OVER_CUT;
        g_rbf[i * R + r] = sinf(arg) * inv * fc;   // fold fcut into rbf
    }
}

// ---------------- SGEMM: C = act(A[M,K] @ B[K,N] + bias), 128x128 tile -------
// Requirements: K % 16 == 0.
template <int ACT>
__global__ __launch_bounds__(256)
void gemm_kernel(const float* __restrict__ A, const float* __restrict__ B,
                 const float* __restrict__ bias, float* __restrict__ C,
                 int M, int N, int K)
{
    constexpr int BM = 128, BN = 128, BK = 16;
    __shared__ float As[BK][BM + 4];
    __shared__ float Bs[BK][BN + 4];

    int tid = threadIdx.x;
    int bm = blockIdx.x * BM;
    int bn = blockIdx.y * BN;
    int tx = tid & 15;          // 0..15, 8 cols each
    int ty = tid >> 4;          // 0..15, 8 rows each

    float acc[8][8] = {};

    for (int k0 = 0; k0 < K; k0 += BK) {
        // A tile: 128 rows x 16 cols, transpose into As[k][m]
        {
            int r = tid >> 2;            // 0..63
            int c = (tid & 3) * 4;       // 0,4,8,12
#pragma unroll
            for (int hh = 0; hh < 2; hh++) {
                int lrow = r + hh * 64;
                int grow = bm + lrow;
                float4 v = make_float4(0.f, 0.f, 0.f, 0.f);
                if (grow < M)
                    v = *reinterpret_cast<const float4*>(A + (size_t)grow * K + k0 + c);
                As[c + 0][lrow] = v.x;
                As[c + 1][lrow] = v.y;
                As[c + 2][lrow] = v.z;
                As[c + 3][lrow] = v.w;
            }
        }
        // B tile: 16 rows x 128 cols
        {
            int r = tid >> 5;            // 0..7
            int c = (tid & 31) * 4;      // 0..124
#pragma unroll
            for (int hh = 0; hh < 2; hh++) {
                int rr = r + hh * 8;
                int gcol = bn + c;
                float4 v = make_float4(0.f, 0.f, 0.f, 0.f);
                if (gcol + 3 < N)
                    v = *reinterpret_cast<const float4*>(B + (size_t)(k0 + rr) * N + gcol);
                *reinterpret_cast<float4*>(&Bs[rr][c]) = v;
            }
        }
        __syncthreads();
#pragma unroll
        for (int kk = 0; kk < BK; kk++) {
            float a[8], b[8];
            *reinterpret_cast<float4*>(&a[0]) = *reinterpret_cast<float4*>(&As[kk][ty * 8]);
            *reinterpret_cast<float4*>(&a[4]) = *reinterpret_cast<float4*>(&As[kk][ty * 8 + 4]);
            *reinterpret_cast<float4*>(&b[0]) = *reinterpret_cast<float4*>(&Bs[kk][tx * 8]);
            *reinterpret_cast<float4*>(&b[4]) = *reinterpret_cast<float4*>(&Bs[kk][tx * 8 + 4]);
#pragma unroll
            for (int i = 0; i < 8; i++)
#pragma unroll
                for (int j = 0; j < 8; j++)
                    acc[i][j] = fmaf(a[i], b[j], acc[i][j]);
        }
        __syncthreads();
    }

#pragma unroll
    for (int i = 0; i < 8; i++) {
        int grow = bm + ty * 8 + i;
        if (grow >= M) continue;
#pragma unroll
        for (int j = 0; j < 8; j++) {
            int gc = bn + tx * 8 + j;
            if (gc >= N) continue;
            float v = acc[i][j] + (bias ? bias[gc] : 0.0f);
            if (ACT == 1) v = silu_f(v);
            C[(size_t)grow * N + gc] = v;
        }
    }
}

// ---------------- message kernel over col-sorted segments --------------------
#define COLS_PER_BLOCK 64
__global__ __launch_bounds__(128)
void msg_kernel(const float* __restrict__ Wf, const float* __restrict__ bf)
{
    int t = threadIdx.x;
    // filter weights for this channel live in registers (exactly 63 floats)
    float w0[R], w1[R], w2[R];
#pragma unroll
    for (int r = 0; r < R; r++) {
        w0[r] = Wf[r * H3 + t];
        w1[r] = Wf[r * H3 + H + t];
        w2[r] = Wf[r * H3 + 2 * H + t];
    }
    float b0 = bf[t], b1 = bf[H + t], b2 = bf[2 * H + t];

    int c0   = blockIdx.x * COLS_PER_BLOCK;
    int cend = min(c0 + COLS_PER_BLOCK, NA);
    for (int c = c0; c < cend; c++) {
        int beg = g_start[c], end = g_start[c + 1];
        if (beg >= end) continue;
        const float* sc  = g_s  + (size_t)c * H3;
        const float* nvc = g_nv + (size_t)c * H3;
        float s0  = sc[t],      s1  = sc[H + t],  s2  = sc[2 * H + t];
        float nv0 = nvc[t],     nv1 = nvc[H + t], nv2 = nvc[2 * H + t];
        for (int i = beg; i < end; i++) {
            float fc = g_fcut[i];
            float ux = g_unit[i * 3 + 0];
            float uy = g_unit[i * 3 + 1];
            float uz = g_unit[i * 3 + 2];
            int row  = g_srow[i];
            float f0 = b0 * fc, f1 = b1 * fc, f2 = b2 * fc;
#pragma unroll
            for (int r = 0; r < R; r++) {
                float rb = __ldg(&g_rbf[i * R + r]);
                f0 = fmaf(rb, w0[r], f0);
                f1 = fmaf(rb, w1[r], f1);
                f2 = fmaf(rb, w2[r], f2);
            }
            float gate_sv = f0 * s0;
            float gate_ev = f1 * s1;
            atomicAdd(&g_ns[(size_t)row * H + t], f2 * s2);
            float* dnr = g_dnv + (size_t)row * H3;
            atomicAdd(&dnr[t],         fmaf(nv0, gate_sv, gate_ev * ux));
            atomicAdd(&dnr[H + t],     fmaf(nv1, gate_sv, gate_ev * uy));
            atomicAdd(&dnr[2 * H + t], fmaf(nv2, gate_sv, gate_ev * uz));
        }
    }
}

// ---------------- nv += dnv; dnv = 0 ----------------------------------------
__global__ void apply_dnv_kernel()
{
    int idx = blockIdx.x * blockDim.x + threadIdx.x;
    int total = NA * H3;
    for (int i = idx; i < total; i += gridDim.x * blockDim.x) {
        g_nv[i] += g_dnv[i];
        g_dnv[i] = 0.0f;
    }
}

// ---------------- Vnorm + concat into mlp_in ---------------------------------
__global__ void vnorm_concat_kernel()
{
    int idx = blockIdx.x * blockDim.x + threadIdx.x;
    if (idx >= NA * H) return;
    int n = idx / H, h = idx - n * H;
    float v0 = g_Vv[(size_t)n * H3 + h];
    float v1 = g_Vv[(size_t)n * H3 + H + h];
    float v2 = g_Vv[(size_t)n * H3 + 2 * H + h];
    float nrm = sqrtf(v0 * v0 + v1 * v1 + v2 * v2);
    g_mlpin[(size_t)n * 2 * H + h]     = g_ns[idx];
    g_mlpin[(size_t)n * 2 * H + H + h] = nrm;
}

// ---------------- final update block -----------------------------------------
__global__ void update_final_kernel()
{
    int idx = blockIdx.x * blockDim.x + threadIdx.x;
    if (idx >= NA * H) return;
    int n = idx / H, h = idx - n * H;
    size_t b3 = (size_t)n * H3;
    float a_vv = g_a[b3 + h];
    float a_sv = g_a[b3 + H + h];
    float a_ss = g_a[b3 + 2 * H + h];
    float uv0 = g_Uv[b3 + h], uv1 = g_Uv[b3 + H + h], uv2 = g_Uv[b3 + 2 * H + h];
    float vv0 = g_Vv[b3 + h], vv1 = g_Vv[b3 + H + h], vv2 = g_Vv[b3 + 2 * H + h];
    g_nv[b3 + h]         += a_vv * uv0;
    g_nv[b3 + H + h]     += a_vv * uv1;
    g_nv[b3 + 2 * H + h] += a_vv * uv2;
    float inner = uv0 * vv0 + uv1 * vv1 + uv2 * vv2;
    g_ns[idx] += inner * a_sv + a_ss;
}

// ---------------- head final reduce: [N,64] @ [64,1] + b ---------------------
__global__ __launch_bounds__(128)
void head_reduce_kernel(const float* __restrict__ W2, const float* __restrict__ b2,
                        float* __restrict__ out)
{
    int warp = threadIdx.x >> 5;
    int lane = threadIdx.x & 31;
    int n = blockIdx.x * 4 + warp;
    if (n >= NA) return;
    float s = g_hid[(size_t)n * 64 + lane]      * W2[lane]
            + g_hid[(size_t)n * 64 + 32 + lane] * W2[32 + lane];
#pragma unroll
    for (int off = 16; off > 0; off >>= 1)
        s += __shfl_xor_sync(0xFFFFFFFFu, s, off);
    if (lane == 0) out[n] = s + b2[0];
}

// ---------------- output tail: pos, edge_index (as float), dist --------------
__global__ void write_outputs_kernel(const float* __restrict__ pos,
                                     const int* __restrict__ eidx,
                                     float* __restrict__ out)
{
    int idx = blockIdx.x * blockDim.x + threadIdx.x;
    const int total = 3 * NA + 2 * NE + NE;
    for (int i = idx; i < total; i += gridDim.x * blockDim.x) {
        if (i < 3 * NA) {
            out[NA + i] = pos[i];
        } else if (i < 3 * NA + 2 * NE) {
            int j = i - 3 * NA;
            out[4 * NA + j] = (float)eidx[j];
        } else {
            int j = i - 3 * NA - 2 * NE;
            out[4 * NA + 2 * NE + j] = g_dist[j];
        }
    }
}

// =============================================================================
extern "C" void kernel_launch(void* const* d_in, const int* in_sizes, int n_in,
                              void* d_out, int out_size)
{
    const int*   z     = (const int*)  d_in[0];
    const float* pos   = (const float*)d_in[1];
    const float* cell  = (const float*)d_in[2];
    const int*   eidx  = (const int*)  d_in[3];
    const int*   coff  = (const int*)  d_in[4];
    const float* embed = (const float*)d_in[5];
    const float* mfW   = (const float*)d_in[6];
    const float* mfb   = (const float*)d_in[7];
    const float* mW1   = (const float*)d_in[8];
    const float* mb1   = (const float*)d_in[9];
    const float* mW2   = (const float*)d_in[10];
    const float* mb2   = (const float*)d_in[11];
    const float* uU    = (const float*)d_in[12];
    const float* uV    = (const float*)d_in[13];
    const float* uW1   = (const float*)d_in[14];
    const float* ub1   = (const float*)d_in[15];
    const float* uW2   = (const float*)d_in[16];
    const float* ub2   = (const float*)d_in[17];
    const float* hW1   = (const float*)d_in[18];
    const float* hb1   = (const float*)d_in[19];
    const float* hW2   = (const float*)d_in[20];
    const float* hb2   = (const float*)d_in[21];
    float* out = (float*)d_out;

    float *p_ns, *p_nv, *p_s, *p_a, *p_hid, *p_mlpin, *p_Uv, *p_Vv;
    cudaGetSymbolAddress((void**)&p_ns,    g_ns);
    cudaGetSymbolAddress((void**)&p_nv,    g_nv);
    cudaGetSymbolAddress((void**)&p_s,     g_s);
    cudaGetSymbolAddress((void**)&p_a,     g_a);
    cudaGetSymbolAddress((void**)&p_hid,   g_hid);
    cudaGetSymbolAddress((void**)&p_mlpin, g_mlpin);
    cudaGetSymbolAddress((void**)&p_Uv,    g_Uv);
    cudaGetSymbolAddress((void**)&p_Vv,    g_Vv);

    init_kernel<<<1024, 256>>>(z, embed);
    hist_kernel<<<(NE + 255) / 256, 256>>>(eidx);
    scan_kernel<<<1, 1024>>>();
    scatter_kernel<<<(NE + 255) / 256, 256>>>(eidx);
    edge_geom_kernel<<<(NE + 255) / 256, 256>>>(pos, cell, eidx, coff);

    dim3 gN128((NA + 127) / 128, 1);        // [N,128]
    dim3 gN384((NA + 127) / 128, 3);        // [N,384]
    dim3 g3N128((3 * NA + 127) / 128, 1);   // [3N,128]
    dim3 gN64((NA + 127) / 128, 1);         // [N,64]

    for (int l = 0; l < 3; l++) {
        // message MLP: s = silu(ns@W1+b1)@W2+b2
        gemm_kernel<1><<<gN128, 256>>>(p_ns, mW1 + (size_t)l * H * H, mb1 + (size_t)l * H,
                                       p_hid, NA, H, H);
        gemm_kernel<0><<<gN384, 256>>>(p_hid, mW2 + (size_t)l * H * H3, mb2 + (size_t)l * H3,
                                       p_s, NA, H3, H);
        // edge messages over col-sorted segments
        msg_kernel<<<(NA + COLS_PER_BLOCK - 1) / COLS_PER_BLOCK, 128>>>(
            mfW + (size_t)l * R * H3, mfb + (size_t)l * H3);
        apply_dnv_kernel<<<1024, 256>>>();

        // update block
        gemm_kernel<0><<<g3N128, 256>>>(p_nv, uU + (size_t)l * H * H, nullptr,
                                        p_Uv, 3 * NA, H, H);
        gemm_kernel<0><<<g3N128, 256>>>(p_nv, uV + (size_t)l * H * H, nullptr,
                                        p_Vv, 3 * NA, H, H);
        vnorm_concat_kernel<<<(NA * H + 255) / 256, 256>>>();
        gemm_kernel<1><<<gN128, 256>>>(p_mlpin, uW1 + (size_t)l * 2 * H * H, ub1 + (size_t)l * H,
                                       p_hid, NA, H, 2 * H);
        gemm_kernel<0><<<gN384, 256>>>(p_hid, uW2 + (size_t)l * H * H3, ub2 + (size_t)l * H3,
                                       p_a, NA, H3, H);
        update_final_kernel<<<(NA * H + 255) / 256, 256>>>();
    }

    // head
    gemm_kernel<1><<<gN64, 256>>>(p_ns, hW1, hb1, p_hid, NA, 64, H);
    head_reduce_kernel<<<(NA + 3) / 4, 128>>>(hW2, hb2, out);

    write_outputs_kernel<<<2048, 256>>>(pos, eidx, out);
}

// round 3
// speedup vs baseline: 1.1525x; 1.1525x over previous
#include <cuda_runtime.h>
#include <cstdint>

#define NA 50000
#define NE 500000
#define H  128
#define R  20
#define H3 (3*H)

static constexpr float PI_F = 3.14159265358979323846f;
static constexpr float PI_OVER_CUT = PI_F / 6.0f;   // pi / CUTOFF

// ---------------- scratch (static device globals; no allocations) ------------
__device__ float g_ns   [NA * H];        // node scalar
__device__ float g_nv   [NA * H3];       // node vector [N,3,H]
__device__ float g_dnv  [NA * H3];       // vector message accumulator (delta)
__device__ float g_s    [NA * H3];       // message MLP output s [N,3H]
__device__ float g_a    [NA * H3];       // update MLP output a [N,3H]
__device__ float g_hid  [NA * H];        // MLP hidden scratch
__device__ float g_mlpin[NA * 2 * H];    // concat(ns, Vnorm)
__device__ float g_Uv   [NA * H3];
__device__ float g_Vv   [NA * H3];
__device__ float g_rbf  [NE * R];        // rbf * fcut  (SORTED order)
__device__ float g_unit [NE * 3];        // (SORTED order)
__device__ float g_fcut [NE];            // (SORTED order)
__device__ float g_dist [NE];            // ORIGINAL edge order (output)

// edge sort-by-col structures
__device__ int g_cnt  [NA + 1];
__device__ int g_start[NA + 1];
__device__ int g_ofs  [NA];
__device__ int g_perm [NE];              // sorted slot -> original edge id
__device__ int g_srow [NE];              // row per sorted slot
__device__ int g_scol [NE];              // col per sorted slot

__device__ __forceinline__ float silu_f(float x) { return x / (1.0f + __expf(-x)); }

// ---------------- init: ns = embed[z], nv = 0, dnv = 0, cnt = 0 --------------
__global__ void init_kernel(const int* __restrict__ z, const float* __restrict__ embed)
{
    int idx = blockIdx.x * blockDim.x + threadIdx.x;
    int total = NA * H3;
    for (int i = idx; i < total; i += gridDim.x * blockDim.x) {
        g_nv[i]  = 0.0f;
        g_dnv[i] = 0.0f;
        if (i < NA * H) {
            int n = i / H, h = i - n * H;
            g_ns[i] = embed[z[n] * H + h];
        }
        if (i <= NA) g_cnt[i] = 0;
    }
}

// ---------------- histogram over col -----------------------------------------
__global__ void hist_kernel(const int* __restrict__ eidx)
{
    int e = blockIdx.x * blockDim.x + threadIdx.x;
    if (e >= NE) return;
    atomicAdd(&g_cnt[eidx[NE + e]], 1);
}

// ---------------- single-block exclusive scan over 50k counts ----------------
__global__ __launch_bounds__(1024) void scan_kernel()
{
    __shared__ int part[1024];
    const int CH = (NA + 1023) / 1024;   // 49
    int t = threadIdx.x;
    int base = t * CH;
    int sum = 0;
    for (int i = 0; i < CH; i++) {
        int idx = base + i;
        if (idx < NA) sum += g_cnt[idx];
    }
    part[t] = sum;
    __syncthreads();
    for (int off = 1; off < 1024; off <<= 1) {
        int v = 0;
        if (t >= off) v = part[t - off];
        __syncthreads();
        part[t] += v;
        __syncthreads();
    }
    int run = (t == 0) ? 0 : part[t - 1];
    for (int i = 0; i < CH; i++) {
        int idx = base + i;
        if (idx < NA) {
            int c = g_cnt[idx];
            g_start[idx] = run;
            g_ofs[idx]   = run;
            run += c;
        }
    }
    if (t == 1023) g_start[NA] = NE;
}

// ---------------- scatter into sorted order ----------------------------------
__global__ void scatter_kernel(const int* __restrict__ eidx)
{
    int e = blockIdx.x * blockDim.x + threadIdx.x;
    if (e >= NE) return;
    int c = eidx[NE + e];
    int p = atomicAdd(&g_ofs[c], 1);
    g_perm[p] = e;
    g_srow[p] = eidx[e];
    g_scol[p] = c;
}

// ---------------- edge geometry into SORTED slots ----------------------------
__global__ void edge_geom_kernel(const float* __restrict__ pos,
                                 const float* __restrict__ cell,
                                 const int*   __restrict__ eidx,
                                 const int*   __restrict__ coff)
{
    int i = blockIdx.x * blockDim.x + threadIdx.x;
    if (i >= NE) return;
    int e   = g_perm[i];
    int row = eidx[e];
    int col = eidx[NE + e];
    float ox = (float)coff[e * 3 + 0];
    float oy = (float)coff[e * 3 + 1];
    float oz = (float)coff[e * 3 + 2];
    float offx = ox * cell[0] + oy * cell[3] + oz * cell[6];
    float offy = ox * cell[1] + oy * cell[4] + oz * cell[7];
    float offz = ox * cell[2] + oy * cell[5] + oz * cell[8];
    float dx = pos[row * 3 + 0] - pos[col * 3 + 0] + offx;
    float dy = pos[row * 3 + 1] - pos[col * 3 + 1] + offy;
    float dz = pos[row * 3 + 2] - pos[col * 3 + 2] + offz;
    float d  = sqrtf(dx * dx + dy * dy + dz * dz);
    float inv = 1.0f / d;
    g_dist[e] = d;                        // original order for output
    g_unit[i * 3 + 0] = dx * inv;
    g_unit[i * 3 + 1] = dy * inv;
    g_unit[i * 3 + 2] = dz * inv;
    float fc = (d < 6.0f) ? 0.5f * (cosf(PI_F * d * (1.0f / 6.0f)) + 1.0f) : 0.0f;
    g_fcut[i] = fc;
#pragma unroll
    for (int r = 0; r < R; r++) {
        float arg = d * (float)(r + 1) * PI_OVER_CUT;
        g_rbf[i * R + r] = sinf(arg) * inv * fc;   // fold fcut into rbf
    }
}

// ---------------- SGEMM: C = act(A[M,K] @ B[K,N] + bias), 128x128 tile -------
// Requirements: K % 16 == 0.
template <int ACT>
__global__ __launch_bounds__(256)
void gemm_kernel(const float* __restrict__ A, const float* __restrict__ B,
                 const float* __restrict__ bias, float* __restrict__ C,
                 int M, int N, int K)
{
    constexpr int BM = 128, BN = 128, BK = 16;
    __shared__ float As[BK][BM + 4];
    __shared__ float Bs[BK][BN + 4];

    int tid = threadIdx.x;
    int bm = blockIdx.x * BM;
    int bn = blockIdx.y * BN;
    int tx = tid & 15;          // 0..15, 8 cols each
    int ty = tid >> 4;          // 0..15, 8 rows each

    float acc[8][8] = {};

    for (int k0 = 0; k0 < K; k0 += BK) {
        // A tile: 128 rows x 16 cols, transpose into As[k][m]
        {
            int r = tid >> 2;            // 0..63
            int c = (tid & 3) * 4;       // 0,4,8,12
#pragma unroll
            for (int hh = 0; hh < 2; hh++) {
                int lrow = r + hh * 64;
                int grow = bm + lrow;
                float4 v = make_float4(0.f, 0.f, 0.f, 0.f);
                if (grow < M)
                    v = *reinterpret_cast<const float4*>(A + (size_t)grow * K + k0 + c);
                As[c + 0][lrow] = v.x;
                As[c + 1][lrow] = v.y;
                As[c + 2][lrow] = v.z;
                As[c + 3][lrow] = v.w;
            }
        }
        // B tile: 16 rows x 128 cols
        {
            int r = tid >> 5;            // 0..7
            int c = (tid & 31) * 4;      // 0..124
#pragma unroll
            for (int hh = 0; hh < 2; hh++) {
                int rr = r + hh * 8;
                int gcol = bn + c;
                float4 v = make_float4(0.f, 0.f, 0.f, 0.f);
                if (gcol + 3 < N)
                    v = *reinterpret_cast<const float4*>(B + (size_t)(k0 + rr) * N + gcol);
                *reinterpret_cast<float4*>(&Bs[rr][c]) = v;
            }
        }
        __syncthreads();
#pragma unroll
        for (int kk = 0; kk < BK; kk++) {
            float a[8], b[8];
            *reinterpret_cast<float4*>(&a[0]) = *reinterpret_cast<float4*>(&As[kk][ty * 8]);
            *reinterpret_cast<float4*>(&a[4]) = *reinterpret_cast<float4*>(&As[kk][ty * 8 + 4]);
            *reinterpret_cast<float4*>(&b[0]) = *reinterpret_cast<float4*>(&Bs[kk][tx * 8]);
            *reinterpret_cast<float4*>(&b[4]) = *reinterpret_cast<float4*>(&Bs[kk][tx * 8 + 4]);
#pragma unroll
            for (int i = 0; i < 8; i++)
#pragma unroll
                for (int j = 0; j < 8; j++)
                    acc[i][j] = fmaf(a[i], b[j], acc[i][j]);
        }
        __syncthreads();
    }

#pragma unroll
    for (int i = 0; i < 8; i++) {
        int grow = bm + ty * 8 + i;
        if (grow >= M) continue;
#pragma unroll
        for (int j = 0; j < 8; j++) {
            int gc = bn + tx * 8 + j;
            if (gc >= N) continue;
            float v = acc[i][j] + (bias ? bias[gc] : 0.0f);
            if (ACT == 1) v = silu_f(v);
            C[(size_t)grow * N + gc] = v;
        }
    }
}

// ---------------- message kernel: edge-parallel over col-SORTED edges --------
#define EPB 32
__global__ __launch_bounds__(128)
void msg_kernel(const float* __restrict__ Wf, const float* __restrict__ bf)
{
    __shared__ float sW[R * H3];     // 30 KB
    __shared__ float sb[H3];
    int t = threadIdx.x;
    for (int i = t; i < R * H3; i += 128) sW[i] = Wf[i];
    for (int i = t; i < H3; i += 128) sb[i] = bf[i];
    __syncthreads();

    float b0 = sb[t], b1 = sb[H + t], b2 = sb[2 * H + t];

    int i0   = blockIdx.x * EPB;
    int iend = min(i0 + EPB, NE);
    int curcol = -1;
    float s0 = 0.f, s1 = 0.f, s2 = 0.f, nv0 = 0.f, nv1 = 0.f, nv2 = 0.f;

    for (int i = i0; i < iend; i++) {
        int col = g_scol[i];
        if (col != curcol) {
            const float* sc  = g_s  + (size_t)col * H3;
            const float* nvc = g_nv + (size_t)col * H3;
            s0  = sc[t];  s1  = sc[H + t];  s2  = sc[2 * H + t];
            nv0 = nvc[t]; nv1 = nvc[H + t]; nv2 = nvc[2 * H + t];
            curcol = col;
        }
        float fc = g_fcut[i];
        float ux = g_unit[i * 3 + 0];
        float uy = g_unit[i * 3 + 1];
        float uz = g_unit[i * 3 + 2];
        int row  = g_srow[i];

        float f0 = b0 * fc, f1 = b1 * fc, f2 = b2 * fc;
#pragma unroll
        for (int r = 0; r < R; r++) {
            float rb = __ldg(&g_rbf[i * R + r]);    // broadcast across warp
            f0 = fmaf(rb, sW[r * H3 + t], f0);
            f1 = fmaf(rb, sW[r * H3 + H + t], f1);
            f2 = fmaf(rb, sW[r * H3 + 2 * H + t], f2);
        }
        float gate_sv = f0 * s0;
        float gate_ev = f1 * s1;

        atomicAdd(&g_ns[(size_t)row * H + t], f2 * s2);
        float* dnr = g_dnv + (size_t)row * H3;
        atomicAdd(&dnr[t],         fmaf(nv0, gate_sv, gate_ev * ux));
        atomicAdd(&dnr[H + t],     fmaf(nv1, gate_sv, gate_ev * uy));
        atomicAdd(&dnr[2 * H + t], fmaf(nv2, gate_sv, gate_ev * uz));
    }
}

// ---------------- nv += dnv; dnv = 0 (float4) --------------------------------
__global__ void apply_dnv_kernel()
{
    int idx = blockIdx.x * blockDim.x + threadIdx.x;
    int total = NA * H3 / 4;
    float4* nv4  = reinterpret_cast<float4*>(g_nv);
    float4* dnv4 = reinterpret_cast<float4*>(g_dnv);
    for (int i = idx; i < total; i += gridDim.x * blockDim.x) {
        float4 a = nv4[i], b = dnv4[i];
        a.x += b.x; a.y += b.y; a.z += b.z; a.w += b.w;
        nv4[i] = a;
        dnv4[i] = make_float4(0.f, 0.f, 0.f, 0.f);
    }
}

// ---------------- Vnorm + concat into mlp_in ---------------------------------
__global__ void vnorm_concat_kernel()
{
    int idx = blockIdx.x * blockDim.x + threadIdx.x;
    if (idx >= NA * H) return;
    int n = idx / H, h = idx - n * H;
    float v0 = g_Vv[(size_t)n * H3 + h];
    float v1 = g_Vv[(size_t)n * H3 + H + h];
    float v2 = g_Vv[(size_t)n * H3 + 2 * H + h];
    float nrm = sqrtf(v0 * v0 + v1 * v1 + v2 * v2);
    g_mlpin[(size_t)n * 2 * H + h]     = g_ns[idx];
    g_mlpin[(size_t)n * 2 * H + H + h] = nrm;
}

// ---------------- final update block -----------------------------------------
__global__ void update_final_kernel()
{
    int idx = blockIdx.x * blockDim.x + threadIdx.x;
    if (idx >= NA * H) return;
    int n = idx / H, h = idx - n * H;
    size_t b3 = (size_t)n * H3;
    float a_vv = g_a[b3 + h];
    float a_sv = g_a[b3 + H + h];
    float a_ss = g_a[b3 + 2 * H + h];
    float uv0 = g_Uv[b3 + h], uv1 = g_Uv[b3 + H + h], uv2 = g_Uv[b3 + 2 * H + h];
    float vv0 = g_Vv[b3 + h], vv1 = g_Vv[b3 + H + h], vv2 = g_Vv[b3 + 2 * H + h];
    g_nv[b3 + h]         += a_vv * uv0;
    g_nv[b3 + H + h]     += a_vv * uv1;
    g_nv[b3 + 2 * H + h] += a_vv * uv2;
    float inner = uv0 * vv0 + uv1 * vv1 + uv2 * vv2;
    g_ns[idx] += inner * a_sv + a_ss;
}

// ---------------- head final reduce: [N,64] @ [64,1] + b ---------------------
__global__ __launch_bounds__(128)
void head_reduce_kernel(const float* __restrict__ W2, const float* __restrict__ b2,
                        float* __restrict__ out)
{
    int warp = threadIdx.x >> 5;
    int lane = threadIdx.x & 31;
    int n = blockIdx.x * 4 + warp;
    if (n >= NA) return;
    float s = g_hid[(size_t)n * 64 + lane]      * W2[lane]
            + g_hid[(size_t)n * 64 + 32 + lane] * W2[32 + lane];
#pragma unroll
    for (int off = 16; off > 0; off >>= 1)
        s += __shfl_xor_sync(0xFFFFFFFFu, s, off);
    if (lane == 0) out[n] = s + b2[0];
}

// ---------------- output tail: pos, edge_index (as float), dist --------------
__global__ void write_outputs_kernel(const float* __restrict__ pos,
                                     const int* __restrict__ eidx,
                                     float* __restrict__ out)
{
    int idx = blockIdx.x * blockDim.x + threadIdx.x;
    const int total = 3 * NA + 2 * NE + NE;
    for (int i = idx; i < total; i += gridDim.x * blockDim.x) {
        if (i < 3 * NA) {
            out[NA + i] = pos[i];
        } else if (i < 3 * NA + 2 * NE) {
            int j = i - 3 * NA;
            out[4 * NA + j] = (float)eidx[j];
        } else {
            int j = i - 3 * NA - 2 * NE;
            out[4 * NA + 2 * NE + j] = g_dist[j];
        }
    }
}

// =============================================================================
extern "C" void kernel_launch(void* const* d_in, const int* in_sizes, int n_in,
                              void* d_out, int out_size)
{
    const int*   z     = (const int*)  d_in[0];
    const float* pos   = (const float*)d_in[1];
    const float* cell  = (const float*)d_in[2];
    const int*   eidx  = (const int*)  d_in[3];
    const int*   coff  = (const int*)  d_in[4];
    const float* embed = (const float*)d_in[5];
    const float* mfW   = (const float*)d_in[6];
    const float* mfb   = (const float*)d_in[7];
    const float* mW1   = (const float*)d_in[8];
    const float* mb1   = (const float*)d_in[9];
    const float* mW2   = (const float*)d_in[10];
    const float* mb2   = (const float*)d_in[11];
    const float* uU    = (const float*)d_in[12];
    const float* uV    = (const float*)d_in[13];
    const float* uW1   = (const float*)d_in[14];
    const float* ub1   = (const float*)d_in[15];
    const float* uW2   = (const float*)d_in[16];
    const float* ub2   = (const float*)d_in[17];
    const float* hW1   = (const float*)d_in[18];
    const float* hb1   = (const float*)d_in[19];
    const float* hW2   = (const float*)d_in[20];
    const float* hb2   = (const float*)d_in[21];
    float* out = (float*)d_out;

    float *p_ns, *p_nv, *p_s, *p_a, *p_hid, *p_mlpin, *p_Uv, *p_Vv;
    cudaGetSymbolAddress((void**)&p_ns,    g_ns);
    cudaGetSymbolAddress((void**)&p_nv,    g_nv);
    cudaGetSymbolAddress((void**)&p_s,     g_s);
    cudaGetSymbolAddress((void**)&p_a,     g_a);
    cudaGetSymbolAddress((void**)&p_hid,   g_hid);
    cudaGetSymbolAddress((void**)&p_mlpin, g_mlpin);
    cudaGetSymbolAddress((void**)&p_Uv,    g_Uv);
    cudaGetSymbolAddress((void**)&p_Vv,    g_Vv);

    init_kernel<<<1024, 256>>>(z, embed);
    hist_kernel<<<(NE + 255) / 256, 256>>>(eidx);
    scan_kernel<<<1, 1024>>>();
    scatter_kernel<<<(NE + 255) / 256, 256>>>(eidx);
    edge_geom_kernel<<<(NE + 255) / 256, 256>>>(pos, cell, eidx, coff);

    dim3 gN128((NA + 127) / 128, 1);        // [N,128]
    dim3 gN384((NA + 127) / 128, 3);        // [N,384]
    dim3 g3N128((3 * NA + 127) / 128, 1);   // [3N,128]
    dim3 gN64((NA + 127) / 128, 1);         // [N,64]

    for (int l = 0; l < 3; l++) {
        // message MLP: s = silu(ns@W1+b1)@W2+b2
        gemm_kernel<1><<<gN128, 256>>>(p_ns, mW1 + (size_t)l * H * H, mb1 + (size_t)l * H,
                                       p_hid, NA, H, H);
        gemm_kernel<0><<<gN384, 256>>>(p_hid, mW2 + (size_t)l * H * H3, mb2 + (size_t)l * H3,
                                       p_s, NA, H3, H);
        // edge messages, edge-parallel over col-sorted stream
        msg_kernel<<<(NE + EPB - 1) / EPB, 128>>>(mfW + (size_t)l * R * H3,
                                                  mfb + (size_t)l * H3);
        apply_dnv_kernel<<<1024, 256>>>();

        // update block
        gemm_kernel<0><<<g3N128, 256>>>(p_nv, uU + (size_t)l * H * H, nullptr,
                                        p_Uv, 3 * NA, H, H);
        gemm_kernel<0><<<g3N128, 256>>>(p_nv, uV + (size_t)l * H * H, nullptr,
                                        p_Vv, 3 * NA, H, H);
        vnorm_concat_kernel<<<(NA * H + 255) / 256, 256>>>();
        gemm_kernel<1><<<gN128, 256>>>(p_mlpin, uW1 + (size_t)l * 2 * H * H, ub1 + (size_t)l * H,
                                       p_hid, NA, H, 2 * H);
        gemm_kernel<0><<<gN384, 256>>>(p_hid, uW2 + (size_t)l * H * H3, ub2 + (size_t)l * H3,
                                       p_a, NA, H3, H);
        update_final_kernel<<<(NA * H + 255) / 256, 256>>>();
    }

    // head
    gemm_kernel<1><<<gN64, 256>>>(p_ns, hW1, hb1, p_hid, NA, 64, H);
    head_reduce_kernel<<<(NA + 3) / 4, 128>>>(hW2, hb2, out);

    write_outputs_kernel<<<2048, 256>>>(pos, eidx, out);
}

// round 4
// speedup vs baseline: 1.4157x; 1.2284x over previous
#include <cuda_runtime.h>
#include <cstdint>

#define NA 50000
#define NE 500000
#define H  128
#define R  20
#define H3 (3*H)

static constexpr float PI_F = 3.14159265358979323846f;
static constexpr float PI_OVER_CUT = PI_F / 6.0f;   // pi / CUTOFF

// ---------------- scratch (static device globals; no allocations) ------------
__device__ float g_ns   [NA * H];        // node scalar
__device__ float g_nv   [NA * H3];       // node vector [N,3,H]
__device__ float g_dnv  [NA * H3];       // vector message accumulator (delta)
__device__ float g_s    [NA * H3];       // message MLP output s [N,3H]
__device__ float g_a    [NA * H3];       // update MLP output a [N,3H]
__device__ float g_hid  [NA * H];        // MLP hidden scratch
__device__ float g_mlpin[NA * 2 * H];    // concat(ns, Vnorm)
__device__ float g_Uv   [NA * H3];
__device__ float g_Vv   [NA * H3];
__device__ float g_rbf  [NE * R];        // rbf * fcut  (ROW-SORTED order)
__device__ float g_unit [NE * 3];        // (SORTED order)
__device__ float g_fcut [NE];            // (SORTED order)
__device__ float g_dist [NE];            // ORIGINAL edge order (output)

// edge sort-by-ROW structures
__device__ int g_cnt  [NA + 1];
__device__ int g_ofs  [NA];
__device__ int g_perm [NE];              // sorted slot -> original edge id
__device__ int g_srow [NE];              // row per sorted slot (sort key)
__device__ int g_scol [NE];              // col per sorted slot

__device__ __forceinline__ float silu_f(float x) { return x / (1.0f + __expf(-x)); }

// ---------------- init: ns = embed[z], nv = 0, dnv = 0, cnt = 0 --------------
__global__ void init_kernel(const int* __restrict__ z, const float* __restrict__ embed)
{
    int idx = blockIdx.x * blockDim.x + threadIdx.x;
    int total = NA * H3;
    for (int i = idx; i < total; i += gridDim.x * blockDim.x) {
        g_nv[i]  = 0.0f;
        g_dnv[i] = 0.0f;
        if (i < NA * H) {
            int n = i / H, h = i - n * H;
            g_ns[i] = embed[z[n] * H + h];
        }
        if (i <= NA) g_cnt[i] = 0;
    }
}

// ---------------- histogram over ROW -----------------------------------------
__global__ void hist_kernel(const int* __restrict__ eidx)
{
    int e = blockIdx.x * blockDim.x + threadIdx.x;
    if (e >= NE) return;
    atomicAdd(&g_cnt[eidx[e]], 1);
}

// ---------------- single-block exclusive scan over 50k counts ----------------
__global__ __launch_bounds__(1024) void scan_kernel()
{
    __shared__ int part[1024];
    const int CH = (NA + 1023) / 1024;   // 49
    int t = threadIdx.x;
    int base = t * CH;
    int sum = 0;
    for (int i = 0; i < CH; i++) {
        int idx = base + i;
        if (idx < NA) sum += g_cnt[idx];
    }
    part[t] = sum;
    __syncthreads();
    for (int off = 1; off < 1024; off <<= 1) {
        int v = 0;
        if (t >= off) v = part[t - off];
        __syncthreads();
        part[t] += v;
        __syncthreads();
    }
    int run = (t == 0) ? 0 : part[t - 1];
    for (int i = 0; i < CH; i++) {
        int idx = base + i;
        if (idx < NA) {
            int c = g_cnt[idx];
            g_ofs[idx] = run;
            run += c;
        }
    }
}

// ---------------- scatter into row-sorted order -------------------------------
__global__ void scatter_kernel(const int* __restrict__ eidx)
{
    int e = blockIdx.x * blockDim.x + threadIdx.x;
    if (e >= NE) return;
    int r = eidx[e];
    int p = atomicAdd(&g_ofs[r], 1);
    g_perm[p] = e;
    g_srow[p] = r;
    g_scol[p] = eidx[NE + e];
}

// ---------------- edge geometry into SORTED slots ----------------------------
__global__ void edge_geom_kernel(const float* __restrict__ pos,
                                 const float* __restrict__ cell,
                                 const int*   __restrict__ eidx,
                                 const int*   __restrict__ coff)
{
    int i = blockIdx.x * blockDim.x + threadIdx.x;
    if (i >= NE) return;
    int e   = g_perm[i];
    int row = eidx[e];
    int col = eidx[NE + e];
    float ox = (float)coff[e * 3 + 0];
    float oy = (float)coff[e * 3 + 1];
    float oz = (float)coff[e * 3 + 2];
    float offx = ox * cell[0] + oy * cell[3] + oz * cell[6];
    float offy = ox * cell[1] + oy * cell[4] + oz * cell[7];
    float offz = ox * cell[2] + oy * cell[5] + oz * cell[8];
    float dx = pos[row * 3 + 0] - pos[col * 3 + 0] + offx;
    float dy = pos[row * 3 + 1] - pos[col * 3 + 1] + offy;
    float dz = pos[row * 3 + 2] - pos[col * 3 + 2] + offz;
    float d  = sqrtf(dx * dx + dy * dy + dz * dz);
    float inv = 1.0f / d;
    g_dist[e] = d;                        // original order for output
    g_unit[i * 3 + 0] = dx * inv;
    g_unit[i * 3 + 1] = dy * inv;
    g_unit[i * 3 + 2] = dz * inv;
    float fc = (d < 6.0f) ? 0.5f * (cosf(PI_F * d * (1.0f / 6.0f)) + 1.0f) : 0.0f;
    g_fcut[i] = fc;
#pragma unroll
    for (int r = 0; r < R; r++) {
        float arg = d * (float)(r + 1) * PI_OVER_CUT;
        g_rbf[i * R + r] = sinf(arg) * inv * fc;   // fold fcut into rbf
    }
}

// ---------------- SGEMM: C = act(A[M,K] @ B[K,N] + bias), 128x128 tile -------
template <int ACT>
__global__ __launch_bounds__(256)
void gemm_kernel(const float* __restrict__ A, const float* __restrict__ B,
                 const float* __restrict__ bias, float* __restrict__ C,
                 int M, int N, int K)
{
    constexpr int BM = 128, BN = 128, BK = 16;
    __shared__ float As[BK][BM + 4];
    __shared__ float Bs[BK][BN + 4];

    int tid = threadIdx.x;
    int bm = blockIdx.x * BM;
    int bn = blockIdx.y * BN;
    int tx = tid & 15;
    int ty = tid >> 4;

    float acc[8][8] = {};

    for (int k0 = 0; k0 < K; k0 += BK) {
        {
            int r = tid >> 2;
            int c = (tid & 3) * 4;
#pragma unroll
            for (int hh = 0; hh < 2; hh++) {
                int lrow = r + hh * 64;
                int grow = bm + lrow;
                float4 v = make_float4(0.f, 0.f, 0.f, 0.f);
                if (grow < M)
                    v = *reinterpret_cast<const float4*>(A + (size_t)grow * K + k0 + c);
                As[c + 0][lrow] = v.x;
                As[c + 1][lrow] = v.y;
                As[c + 2][lrow] = v.z;
                As[c + 3][lrow] = v.w;
            }
        }
        {
            int r = tid >> 5;
            int c = (tid & 31) * 4;
#pragma unroll
            for (int hh = 0; hh < 2; hh++) {
                int rr = r + hh * 8;
                int gcol = bn + c;
                float4 v = make_float4(0.f, 0.f, 0.f, 0.f);
                if (gcol + 3 < N)
                    v = *reinterpret_cast<const float4*>(B + (size_t)(k0 + rr) * N + gcol);
                *reinterpret_cast<float4*>(&Bs[rr][c]) = v;
            }
        }
        __syncthreads();
#pragma unroll
        for (int kk = 0; kk < BK; kk++) {
            float a[8], b[8];
            *reinterpret_cast<float4*>(&a[0]) = *reinterpret_cast<float4*>(&As[kk][ty * 8]);
            *reinterpret_cast<float4*>(&a[4]) = *reinterpret_cast<float4*>(&As[kk][ty * 8 + 4]);
            *reinterpret_cast<float4*>(&b[0]) = *reinterpret_cast<float4*>(&Bs[kk][tx * 8]);
            *reinterpret_cast<float4*>(&b[4]) = *reinterpret_cast<float4*>(&Bs[kk][tx * 8 + 4]);
#pragma unroll
            for (int i = 0; i < 8; i++)
#pragma unroll
                for (int j = 0; j < 8; j++)
                    acc[i][j] = fmaf(a[i], b[j], acc[i][j]);
        }
        __syncthreads();
    }

#pragma unroll
    for (int i = 0; i < 8; i++) {
        int grow = bm + ty * 8 + i;
        if (grow >= M) continue;
#pragma unroll
        for (int j = 0; j < 8; j++) {
            int gc = bn + tx * 8 + j;
            if (gc >= N) continue;
            float v = acc[i][j] + (bias ? bias[gc] : 0.0f);
            if (ACT == 1) v = silu_f(v);
            C[(size_t)grow * N + gc] = v;
        }
    }
}

// ---------------- message kernel: row-sorted segmented reduction --------------
// Block handles EPB consecutive row-sorted edge slots. Per-thread (=channel)
// register accumulators, flushed once per row segment. Rows fully inside the
// block's range -> plain store; straddling rows -> atomicAdd.
#define EPB 128
__global__ __launch_bounds__(128)
void msg_kernel(const float* __restrict__ Wf, const float* __restrict__ bf)
{
    __shared__ float rbf_s[EPB * R];             // 10 KB
    __shared__ int   se_row[EPB], se_col[EPB];
    __shared__ float se_fcut[EPB], se_ux[EPB], se_uy[EPB], se_uz[EPB];

    const int t = threadIdx.x;
    const int iBeg = blockIdx.x * EPB;
    const int n = min(EPB, NE - iBeg);

    // cooperative stage of per-edge data
    for (int j = t; j < n * R; j += 128) rbf_s[j] = g_rbf[(size_t)iBeg * R + j];
    if (t < n) {
        se_row[t]  = g_srow[iBeg + t];
        se_col[t]  = g_scol[iBeg + t];
        se_fcut[t] = g_fcut[iBeg + t];
        se_ux[t]   = g_unit[(iBeg + t) * 3 + 0];
        se_uy[t]   = g_unit[(iBeg + t) * 3 + 1];
        se_uz[t]   = g_unit[(iBeg + t) * 3 + 2];
    }

    // filter weights for this channel in registers (60 floats)
    float w0[R], w1[R], w2[R];
#pragma unroll
    for (int r = 0; r < R; r++) {
        w0[r] = Wf[r * H3 + t];
        w1[r] = Wf[r * H3 + H + t];
        w2[r] = Wf[r * H3 + 2 * H + t];
    }
    const float b0 = bf[t], b1 = bf[H + t], b2 = bf[2 * H + t];
    __syncthreads();

    int currow = se_row[0];
    bool startsBefore = (iBeg > 0) && (g_srow[iBeg - 1] == currow);
    float a0 = 0.f, a1 = 0.f, a2 = 0.f, a3 = 0.f;

    for (int ei = 0; ei < n; ei++) {
        int row = se_row[ei];
        if (row != currow) {
            // flush previous segment (ends inside block)
            float* dnr = g_dnv + (size_t)currow * H3;
            if (startsBefore) {
                atomicAdd(&g_ns[(size_t)currow * H + t], a3);
                atomicAdd(&dnr[t], a0);
                atomicAdd(&dnr[H + t], a1);
                atomicAdd(&dnr[2 * H + t], a2);
            } else {
                g_ns[(size_t)currow * H + t] += a3;
                dnr[t] = a0; dnr[H + t] = a1; dnr[2 * H + t] = a2;
            }
            currow = row; startsBefore = false;
            a0 = a1 = a2 = a3 = 0.f;
        }
        float fc = se_fcut[ei];
        int col  = se_col[ei];
        const float* sc  = g_s  + (size_t)col * H3;
        const float* nvc = g_nv + (size_t)col * H3;
        float s0 = sc[t], s1 = sc[H + t], s2 = sc[2 * H + t];
        float nv0 = nvc[t], nv1 = nvc[H + t], nv2 = nvc[2 * H + t];

        float f0 = b0 * fc, f1 = b1 * fc, f2 = b2 * fc;
#pragma unroll
        for (int r = 0; r < R; r++) {
            float rb = rbf_s[ei * R + r];
            f0 = fmaf(rb, w0[r], f0);
            f1 = fmaf(rb, w1[r], f1);
            f2 = fmaf(rb, w2[r], f2);
        }
        float gate_sv = f0 * s0;
        float gate_ev = f1 * s1;
        a3 += f2 * s2;
        a0 += fmaf(nv0, gate_sv, gate_ev * se_ux[ei]);
        a1 += fmaf(nv1, gate_sv, gate_ev * se_uy[ei]);
        a2 += fmaf(nv2, gate_sv, gate_ev * se_uz[ei]);
    }

    // final flush
    bool endsAfter = (iBeg + n < NE) && (g_srow[iBeg + n] == currow);
    float* dnr = g_dnv + (size_t)currow * H3;
    if (startsBefore || endsAfter) {
        atomicAdd(&g_ns[(size_t)currow * H + t], a3);
        atomicAdd(&dnr[t], a0);
        atomicAdd(&dnr[H + t], a1);
        atomicAdd(&dnr[2 * H + t], a2);
    } else {
        g_ns[(size_t)currow * H + t] += a3;
        dnr[t] = a0; dnr[H + t] = a1; dnr[2 * H + t] = a2;
    }
}

// ---------------- nv += dnv; dnv = 0 (float4) --------------------------------
__global__ void apply_dnv_kernel()
{
    int idx = blockIdx.x * blockDim.x + threadIdx.x;
    int total = NA * H3 / 4;
    float4* nv4  = reinterpret_cast<float4*>(g_nv);
    float4* dnv4 = reinterpret_cast<float4*>(g_dnv);
    for (int i = idx; i < total; i += gridDim.x * blockDim.x) {
        float4 a = nv4[i], b = dnv4[i];
        a.x += b.x; a.y += b.y; a.z += b.z; a.w += b.w;
        nv4[i] = a;
        dnv4[i] = make_float4(0.f, 0.f, 0.f, 0.f);
    }
}

// ---------------- Vnorm + concat into mlp_in ---------------------------------
__global__ void vnorm_concat_kernel()
{
    int idx = blockIdx.x * blockDim.x + threadIdx.x;
    if (idx >= NA * H) return;
    int n = idx / H, h = idx - n * H;
    float v0 = g_Vv[(size_t)n * H3 + h];
    float v1 = g_Vv[(size_t)n * H3 + H + h];
    float v2 = g_Vv[(size_t)n * H3 + 2 * H + h];
    float nrm = sqrtf(v0 * v0 + v1 * v1 + v2 * v2);
    g_mlpin[(size_t)n * 2 * H + h]     = g_ns[idx];
    g_mlpin[(size_t)n * 2 * H + H + h] = nrm;
}

// ---------------- final update block -----------------------------------------
__global__ void update_final_kernel()
{
    int idx = blockIdx.x * blockDim.x + threadIdx.x;
    if (idx >= NA * H) return;
    int n = idx / H, h = idx - n * H;
    size_t b3 = (size_t)n * H3;
    float a_vv = g_a[b3 + h];
    float a_sv = g_a[b3 + H + h];
    float a_ss = g_a[b3 + 2 * H + h];
    float uv0 = g_Uv[b3 + h], uv1 = g_Uv[b3 + H + h], uv2 = g_Uv[b3 + 2 * H + h];
    float vv0 = g_Vv[b3 + h], vv1 = g_Vv[b3 + H + h], vv2 = g_Vv[b3 + 2 * H + h];
    g_nv[b3 + h]         += a_vv * uv0;
    g_nv[b3 + H + h]     += a_vv * uv1;
    g_nv[b3 + 2 * H + h] += a_vv * uv2;
    float inner = uv0 * vv0 + uv1 * vv1 + uv2 * vv2;
    g_ns[idx] += inner * a_sv + a_ss;
}

// ---------------- head final reduce: [N,64] @ [64,1] + b ---------------------
__global__ __launch_bounds__(128)
void head_reduce_kernel(const float* __restrict__ W2, const float* __restrict__ b2,
                        float* __restrict__ out)
{
    int warp = threadIdx.x >> 5;
    int lane = threadIdx.x & 31;
    int n = blockIdx.x * 4 + warp;
    if (n >= NA) return;
    float s = g_hid[(size_t)n * 64 + lane]      * W2[lane]
            + g_hid[(size_t)n * 64 + 32 + lane] * W2[32 + lane];
#pragma unroll
    for (int off = 16; off > 0; off >>= 1)
        s += __shfl_xor_sync(0xFFFFFFFFu, s, off);
    if (lane == 0) out[n] = s + b2[0];
}

// ---------------- output tail: pos, edge_index (as float), dist --------------
__global__ void write_outputs_kernel(const float* __restrict__ pos,
                                     const int* __restrict__ eidx,
                                     float* __restrict__ out)
{
    int idx = blockIdx.x * blockDim.x + threadIdx.x;
    const int total = 3 * NA + 2 * NE + NE;
    for (int i = idx; i < total; i += gridDim.x * blockDim.x) {
        if (i < 3 * NA) {
            out[NA + i] = pos[i];
        } else if (i < 3 * NA + 2 * NE) {
            int j = i - 3 * NA;
            out[4 * NA + j] = (float)eidx[j];
        } else {
            int j = i - 3 * NA - 2 * NE;
            out[4 * NA + 2 * NE + j] = g_dist[j];
        }
    }
}

// =============================================================================
extern "C" void kernel_launch(void* const* d_in, const int* in_sizes, int n_in,
                              void* d_out, int out_size)
{
    const int*   z     = (const int*)  d_in[0];
    const float* pos   = (const float*)d_in[1];
    const float* cell  = (const float*)d_in[2];
    const int*   eidx  = (const int*)  d_in[3];
    const int*   coff  = (const int*)  d_in[4];
    const float* embed = (const float*)d_in[5];
    const float* mfW   = (const float*)d_in[6];
    const float* mfb   = (const float*)d_in[7];
    const float* mW1   = (const float*)d_in[8];
    const float* mb1   = (const float*)d_in[9];
    const float* mW2   = (const float*)d_in[10];
    const float* mb2   = (const float*)d_in[11];
    const float* uU    = (const float*)d_in[12];
    const float* uV    = (const float*)d_in[13];
    const float* uW1   = (const float*)d_in[14];
    const float* ub1   = (const float*)d_in[15];
    const float* uW2   = (const float*)d_in[16];
    const float* ub2   = (const float*)d_in[17];
    const float* hW1   = (const float*)d_in[18];
    const float* hb1   = (const float*)d_in[19];
    const float* hW2   = (const float*)d_in[20];
    const float* hb2   = (const float*)d_in[21];
    float* out = (float*)d_out;

    float *p_ns, *p_nv, *p_s, *p_a, *p_hid, *p_mlpin, *p_Uv, *p_Vv;
    cudaGetSymbolAddress((void**)&p_ns,    g_ns);
    cudaGetSymbolAddress((void**)&p_nv,    g_nv);
    cudaGetSymbolAddress((void**)&p_s,     g_s);
    cudaGetSymbolAddress((void**)&p_a,     g_a);
    cudaGetSymbolAddress((void**)&p_hid,   g_hid);
    cudaGetSymbolAddress((void**)&p_mlpin, g_mlpin);
    cudaGetSymbolAddress((void**)&p_Uv,    g_Uv);
    cudaGetSymbolAddress((void**)&p_Vv,    g_Vv);

    init_kernel<<<1024, 256>>>(z, embed);
    hist_kernel<<<(NE + 255) / 256, 256>>>(eidx);
    scan_kernel<<<1, 1024>>>();
    scatter_kernel<<<(NE + 255) / 256, 256>>>(eidx);
    edge_geom_kernel<<<(NE + 255) / 256, 256>>>(pos, cell, eidx, coff);

    dim3 gN128((NA + 127) / 128, 1);        // [N,128]
    dim3 gN384((NA + 127) / 128, 3);        // [N,384]
    dim3 g3N128((3 * NA + 127) / 128, 1);   // [3N,128]
    dim3 gN64((NA + 127) / 128, 1);         // [N,64]

    for (int l = 0; l < 3; l++) {
        gemm_kernel<1><<<gN128, 256>>>(p_ns, mW1 + (size_t)l * H * H, mb1 + (size_t)l * H,
                                       p_hid, NA, H, H);
        gemm_kernel<0><<<gN384, 256>>>(p_hid, mW2 + (size_t)l * H * H3, mb2 + (size_t)l * H3,
                                       p_s, NA, H3, H);
        msg_kernel<<<(NE + EPB - 1) / EPB, 128>>>(mfW + (size_t)l * R * H3,
                                                  mfb + (size_t)l * H3);
        apply_dnv_kernel<<<1024, 256>>>();

        gemm_kernel<0><<<g3N128, 256>>>(p_nv, uU + (size_t)l * H * H, nullptr,
                                        p_Uv, 3 * NA, H, H);
        gemm_kernel<0><<<g3N128, 256>>>(p_nv, uV + (size_t)l * H * H, nullptr,
                                        p_Vv, 3 * NA, H, H);
        vnorm_concat_kernel<<<(NA * H + 255) / 256, 256>>>();
        gemm_kernel<1><<<gN128, 256>>>(p_mlpin, uW1 + (size_t)l * 2 * H * H, ub1 + (size_t)l * H,
                                       p_hid, NA, H, 2 * H);
        gemm_kernel<0><<<gN384, 256>>>(p_hid, uW2 + (size_t)l * H * H3, ub2 + (size_t)l * H3,
                                       p_a, NA, H3, H);
        update_final_kernel<<<(NA * H + 255) / 256, 256>>>();
    }

    gemm_kernel<1><<<gN64, 256>>>(p_ns, hW1, hb1, p_hid, NA, 64, H);
    head_reduce_kernel<<<(NA + 3) / 4, 128>>>(hW2, hb2, out);

    write_outputs_kernel<<<2048, 256>>>(pos, eidx, out);
}